// round 7
// baseline (speedup 1.0000x reference)
#include <cuda_runtime.h>

// Problem constants
#define BB   4
#define HH   56
#define WW   56
#define CC   128
#define NHD  4
#define HD   32
#define KS   7
#define NB   3              // neighborhood radius
#define MTOK (BB*HH*WW)     // 12544
#define QKVN (3*CC)         // 384
#define SCALE 0.17677669529663687f   // 1/sqrt(32)

// Scratch (device globals; no allocation anywhere)
__device__ float g_qkv[MTOK * QKVN];   // [tok][3*C]
__device__ float g_att[MTOK * CC];     // [tok][C]

// cp.async helpers (sm_80+; fine on sm_103a)
__device__ __forceinline__ void cp_async16(void* smem_dst, const void* gmem_src) {
    unsigned s = (unsigned)__cvta_generic_to_shared(smem_dst);
    asm volatile("cp.async.cg.shared.global [%0], [%1], 16;\n" :: "r"(s), "l"(gmem_src));
}
__device__ __forceinline__ void cp_commit() {
    asm volatile("cp.async.commit_group;\n");
}
template<int N>
__device__ __forceinline__ void cp_wait() {
    asm volatile("cp.async.wait_group %0;\n" :: "n"(N));
}

// ----------------------------------------------------------------------------
// fp32 GEMM: C[M,N] = A[M,K] @ B[K,N] + bias[N]
// BM x BN tile, BK=16, 256 threads, TM x TN microtile, 2-stage pipeline:
//   A: LDG -> regs (prefetch) -> STS transposed   (overlapped with compute)
//   B: cp.async gmem -> smem                      (overlapped with compute)
// Requires: (BM/TM)*(BN/TN)==256, M%BM==0, N%BN==0, K%16==0, TM%4==0, TN%4==0,
//           BM%64==0, BN is 64 or 128.
// ----------------------------------------------------------------------------
template<int BM, int BN, int TM, int TN>
__global__ __launch_bounds__(256) void gemm_bias_kernel(
    const float* __restrict__ A, const float* __restrict__ B,
    const float* __restrict__ bias, float* __restrict__ C,
    int M, int N, int K)
{
    constexpr int BK  = 16;
    constexpr int PAD = 4;
    __shared__ float As[2][BK][BM + PAD];   // [k][m] transposed
    __shared__ float Bs[2][BK][BN];         // [k][n]

    const int tid = threadIdx.x;
    const int tn  = tid % (BN / TN);
    const int tm  = tid / (BN / TN);
    const int rowBase = blockIdx.y * BM;
    const int colBase = blockIdx.x * BN;

    // A loader: 4 threads per row (float4 along k), 64 rows per pass
    const int lm0 = tid >> 2;              // 0..63
    const int lk4 = (tid & 3) * 4;         // 0,4,8,12
    constexpr int A_PASSES = BM / 64;

    // B loader: BN/4 threads per k-row, one 16B cp.async each
    const int bn4 = (tid % (BN / 4)) * 4;
    const int bk0 = tid / (BN / 4);
    constexpr int B_KROWS = 256 / (BN / 4);
    constexpr int B_PASSES = BK / B_KROWS;

    const int nTiles = K / BK;

    float acc[TM][TN];
    #pragma unroll
    for (int i = 0; i < TM; i++)
        #pragma unroll
        for (int j = 0; j < TN; j++) acc[i][j] = 0.f;

    float4 aReg[A_PASSES];

    // ---- prologue: tile 0 ----
    #pragma unroll
    for (int p = 0; p < A_PASSES; p++)
        aReg[p] = *(const float4*)&A[(rowBase + lm0 + p * 64) * K + 0 + lk4];
    #pragma unroll
    for (int p = 0; p < B_PASSES; p++) {
        const int bk = bk0 + p * B_KROWS;
        cp_async16(&Bs[0][bk][bn4], &B[(0 + bk) * N + colBase + bn4]);
    }
    cp_commit();
    #pragma unroll
    for (int p = 0; p < A_PASSES; p++) {
        const int lm = lm0 + p * 64;
        As[0][lk4 + 0][lm] = aReg[p].x;
        As[0][lk4 + 1][lm] = aReg[p].y;
        As[0][lk4 + 2][lm] = aReg[p].z;
        As[0][lk4 + 3][lm] = aReg[p].w;
    }

    for (int t = 0; t < nTiles; t++) {
        const int cur = t & 1, nxt = cur ^ 1;
        const bool more = (t + 1 < nTiles);

        if (more) {
            const int k0 = (t + 1) * BK;
            #pragma unroll
            for (int p = 0; p < A_PASSES; p++)
                aReg[p] = *(const float4*)&A[(rowBase + lm0 + p * 64) * K + k0 + lk4];
            #pragma unroll
            for (int p = 0; p < B_PASSES; p++) {
                const int bk = bk0 + p * B_KROWS;
                cp_async16(&Bs[nxt][bk][bn4], &B[(k0 + bk) * N + colBase + bn4]);
            }
            cp_commit();
            cp_wait<1>();   // current tile's B complete, next stays in flight
        } else {
            cp_wait<0>();
        }
        __syncthreads();

        #pragma unroll
        for (int kk = 0; kk < BK; kk++) {
            float ar[TM], br[TN];
            #pragma unroll
            for (int i4 = 0; i4 < TM; i4 += 4) {
                float4 v = *(const float4*)&As[cur][kk][tm * TM + i4];
                ar[i4 + 0] = v.x; ar[i4 + 1] = v.y; ar[i4 + 2] = v.z; ar[i4 + 3] = v.w;
            }
            #pragma unroll
            for (int j4 = 0; j4 < TN; j4 += 4) {
                float4 v = *(const float4*)&Bs[cur][kk][tn * TN + j4];
                br[j4 + 0] = v.x; br[j4 + 1] = v.y; br[j4 + 2] = v.z; br[j4 + 3] = v.w;
            }
            #pragma unroll
            for (int i = 0; i < TM; i++)
                #pragma unroll
                for (int j = 0; j < TN; j++)
                    acc[i][j] += ar[i] * br[j];
        }
        __syncthreads();

        if (more) {
            #pragma unroll
            for (int p = 0; p < A_PASSES; p++) {
                const int lm = lm0 + p * 64;
                As[nxt][lk4 + 0][lm] = aReg[p].x;
                As[nxt][lk4 + 1][lm] = aReg[p].y;
                As[nxt][lk4 + 2][lm] = aReg[p].z;
                As[nxt][lk4 + 3][lm] = aReg[p].w;
            }
        }
    }

    float bv[TN];
    #pragma unroll
    for (int j = 0; j < TN; j++) bv[j] = bias[colBase + tn * TN + j];

    #pragma unroll
    for (int i = 0; i < TM; i++) {
        #pragma unroll
        for (int j4 = 0; j4 < TN; j4 += 4) {
            float4 o;
            o.x = acc[i][j4 + 0] + bv[j4 + 0];
            o.y = acc[i][j4 + 1] + bv[j4 + 1];
            o.z = acc[i][j4 + 2] + bv[j4 + 2];
            o.w = acc[i][j4 + 3] + bv[j4 + 3];
            *(float4*)&C[(rowBase + tm * TM + i) * N + colBase + tn * TN + j4] = o;
        }
    }
}

// ----------------------------------------------------------------------------
// Neighborhood attention (byte-identical to passing R6 kernel — control group).
// ----------------------------------------------------------------------------
#define TQ   7
#define WIN  13
#define WPOS 169

__global__ __launch_bounds__(64) void natten_kernel(
    const float* __restrict__ qkv, const float* __restrict__ rpb,
    float* __restrict__ o)
{
    __shared__ float Ks[HD * WPOS];   // 21.6 KB
    __shared__ float Vs[HD * WPOS];   // 21.6 KB
    __shared__ float Bsm[WPOS];       // rpb for this head

    const int tid = threadIdx.x;
    const int bn  = blockIdx.y;
    const int n   = bn & 3;
    const int b   = bn >> 2;
    const int ty  = blockIdx.x >> 3;
    const int tx  = blockIdx.x & 7;
    const int ti0 = ty * TQ;
    const int tj0 = tx * TQ;

    const int wi0 = max(ti0 - NB, 0);
    const int wi1 = min(ti0 + NB, HH - KS) + (KS - 1);
    const int wj0 = max(tj0 - NB, 0);
    const int wj1 = min(tj0 + NB, WW - KS) + (KS - 1);
    const int nr = wi1 - wi0 + 1;   // <= 13
    const int nc = wj1 - wj0 + 1;   // <= 13

    for (int i = tid; i < WPOS; i += 64) Bsm[i] = rpb[n * WPOS + i];

    const int npos = nr * nc;
    for (int idx = tid; idx < npos * 8; idx += 64) {
        int pos = idx >> 3, f = idx & 7;
        int r = pos / nc, c = pos - r * nc;
        int tok = (b * HH + wi0 + r) * WW + (wj0 + c);
        const float* base = qkv + tok * QKVN + n * HD + f * 4;
        float4 kv = *(const float4*)(base + CC);
        float4 vv = *(const float4*)(base + 2 * CC);
        int spos = r * WIN + c;
        Ks[(f * 4 + 0) * WPOS + spos] = kv.x;
        Ks[(f * 4 + 1) * WPOS + spos] = kv.y;
        Ks[(f * 4 + 2) * WPOS + spos] = kv.z;
        Ks[(f * 4 + 3) * WPOS + spos] = kv.w;
        Vs[(f * 4 + 0) * WPOS + spos] = vv.x;
        Vs[(f * 4 + 1) * WPOS + spos] = vv.y;
        Vs[(f * 4 + 2) * WPOS + spos] = vv.z;
        Vs[(f * 4 + 3) * WPOS + spos] = vv.w;
    }
    __syncthreads();

    if (tid >= TQ * TQ) return;

    const int qi = tid / TQ, qj = tid - (tid / TQ) * TQ;
    const int i = ti0 + qi, j = tj0 + qj;
    const int si = min(max(i - NB, 0), HH - KS);
    const int sj = min(max(j - NB, 0), WW - KS);
    const int pbase = (si - wi0) * WIN + (sj - wj0);
    const int bbase = (si - i + 2 * NB) * WIN + (sj - j + 2 * NB);
    const int tok = (b * HH + i) * WW + j;

    float q[HD];
    {
        const float4* qp = (const float4*)(qkv + tok * QKVN + n * HD);
        #pragma unroll
        for (int f = 0; f < 8; f++) {
            float4 t = qp[f];
            q[4 * f + 0] = t.x * SCALE;
            q[4 * f + 1] = t.y * SCALE;
            q[4 * f + 2] = t.z * SCALE;
            q[4 * f + 3] = t.w * SCALE;
        }
    }

    float sc[KS * KS];
    float mx = -1e30f;
    #pragma unroll
    for (int p = 0; p < KS; p++) {
        #pragma unroll
        for (int r = 0; r < KS; r++) {
            const int pos = pbase + p * WIN + r;
            float s = 0.f;
            #pragma unroll
            for (int d = 0; d < HD; d++) s += q[d] * Ks[d * WPOS + pos];
            s += Bsm[bbase + p * WIN + r];
            sc[p * KS + r] = s;
            mx = fmaxf(mx, s);
        }
    }

    float sum = 0.f;
    #pragma unroll
    for (int t = 0; t < KS * KS; t++) {
        sc[t] = __expf(sc[t] - mx);
        sum += sc[t];
    }
    float acc[HD];
    #pragma unroll
    for (int d = 0; d < HD; d++) acc[d] = 0.f;
    #pragma unroll
    for (int p = 0; p < KS; p++) {
        #pragma unroll
        for (int r = 0; r < KS; r++) {
            const float w = sc[p * KS + r];
            const int pos = pbase + p * WIN + r;
            #pragma unroll
            for (int d = 0; d < HD; d++) acc[d] += w * Vs[d * WPOS + pos];
        }
    }
    const float inv = 1.f / sum;
    float* op = o + tok * CC + n * HD;
    #pragma unroll
    for (int f = 0; f < 8; f++) {
        float4 t;
        t.x = acc[4 * f + 0] * inv;
        t.y = acc[4 * f + 1] * inv;
        t.z = acc[4 * f + 2] * inv;
        t.w = acc[4 * f + 3] * inv;
        *(float4*)(op + 4 * f) = t;
    }
}

// ----------------------------------------------------------------------------
extern "C" void kernel_launch(void* const* d_in, const int* in_sizes, int n_in,
                              void* d_out, int out_size)
{
    const float* x      = (const float*)d_in[0];
    const float* w_qkv  = (const float*)d_in[1];
    const float* b_qkv  = (const float*)d_in[2];
    const float* rpb    = (const float*)d_in[3];
    const float* w_proj = (const float*)d_in[4];
    const float* b_proj = (const float*)d_in[5];
    float* out = (float*)d_out;

    float *qkv, *att;
    cudaGetSymbolAddress((void**)&qkv, g_qkv);
    cudaGetSymbolAddress((void**)&att, g_att);

    // 1) qkv = x @ w_qkv + b_qkv   (M=12544, N=384, K=128)  -> 98 x 3 CTAs
    dim3 g1(QKVN / 128, MTOK / 128);
    gemm_bias_kernel<128, 128, 8, 8><<<g1, 256>>>(x, w_qkv, b_qkv, qkv, MTOK, QKVN, CC);

    // 2) neighborhood attention -> att [tok, C]
    dim3 g2(64, BB * NHD);   // 8x8 tiles, b*nh
    natten_kernel<<<g2, 64>>>(qkv, rpb, att);

    // 3) out = att @ w_proj + b_proj  (M=12544, N=128, K=128) -> 196 CTAs
    dim3 g3(CC / 64, MTOK / 128);
    gemm_bias_kernel<128, 64, 8, 4><<<g3, 256>>>(att, w_proj, b_proj, out, MTOK, CC, CC);
}

// round 12
// speedup vs baseline: 1.1659x; 1.1659x over previous
#include <cuda_runtime.h>
#include <cuda_bf16.h>
#include <cstdint>

// Problem constants
#define BB   4
#define HH   56
#define WW   56
#define CC   128
#define NHD  4
#define HD   32
#define KS   7
#define NB   3
#define MTOK (BB*HH*WW)     // 12544
#define QKVN (3*CC)         // 384
#define GK   128            // GEMM K (= CC)
#define SCALE 0.17677669529663687f

// ---------------- scratch (device globals, 16B aligned via uint4) ----------
__device__ uint4 g_xhi_[MTOK*CC*2/16];     // bf16 [MTOK][128]
__device__ uint4 g_xlo_[MTOK*CC*2/16];
__device__ uint4 g_wqh_[QKVN*GK*2/16];     // bf16 [384][128]  (w_qkv^T hi)
__device__ uint4 g_wql_[QKVN*GK*2/16];
__device__ uint4 g_wph_[CC*GK*2/16];       // bf16 [128][128]  (w_proj^T hi)
__device__ uint4 g_wpl_[CC*GK*2/16];
__device__ uint4 g_ahi_[MTOK*CC*2/16];     // att hi  bf16 [MTOK][128]
__device__ uint4 g_alo_[MTOK*CC*2/16];     // att lo
__device__ float g_qkv[MTOK * QKVN];       // fp32 qkv for natten

// ---------------- helpers ---------------------------------------------------
__device__ __forceinline__ void cp_async16(uint32_t smem_dst, const void* gmem_src) {
    asm volatile("cp.async.cg.shared.global [%0], [%1], 16;\n" :: "r"(smem_dst), "l"(gmem_src));
}
__device__ __forceinline__ void cp_commit() { asm volatile("cp.async.commit_group;\n"); }
template<int N> __device__ __forceinline__ void cp_wait() {
    asm volatile("cp.async.wait_group %0;\n" :: "n"(N));
}
__device__ __forceinline__ void mma_bf16(float* c, const uint32_t* a, const uint32_t* b) {
    asm volatile(
        "mma.sync.aligned.m16n8k16.row.col.f32.bf16.bf16.f32 "
        "{%0,%1,%2,%3}, {%4,%5,%6,%7}, {%8,%9}, {%0,%1,%2,%3};\n"
        : "+f"(c[0]), "+f"(c[1]), "+f"(c[2]), "+f"(c[3])
        : "r"(a[0]), "r"(a[1]), "r"(a[2]), "r"(a[3]), "r"(b[0]), "r"(b[1]));
}

// Smem tile geometry: 128 rows x 128 bf16, row padded to 136 bf16 (272 B, 68 words).
// Fragment LDS bank = (row*68 + w) mod 32 with row multiples of g: 68 mod 32 = 4
// -> bank = 4g + t (+const): conflict-free across the warp.
#define TPITCH_W 68                 // words per row
#define TBYTES   34816              // 128 * 272
#define SM_TOTAL (4 * TBYTES)       // Ahi, Alo, Bhi, Blo

// ---------------------------------------------------------------------------
// Split-bf16 tensor-core GEMM via mma.sync (family-stable PTX).
// C[M, Ntot](fp32) = A[M,128] x B[Ntot,128]^T + bias,
// where A,B given as bf16 (hi, lo):  D = Ahi*Bhi + Ahi*Blo + Alo*Bhi.
// One 128x128 tile per CTA, 256 threads = 8 warps of 32x64.
// ---------------------------------------------------------------------------
__global__ __launch_bounds__(256) void gemm_mma_kernel(
    const __nv_bfloat16* __restrict__ Ahi, const __nv_bfloat16* __restrict__ Alo,
    const __nv_bfloat16* __restrict__ Bhi, const __nv_bfloat16* __restrict__ Blo,
    const float* __restrict__ bias, float* __restrict__ C, int Ntot)
{
    extern __shared__ char dsm[];
    const uint32_t sb = (uint32_t)__cvta_generic_to_shared(dsm);
    const uint32_t sAhi = sb, sAlo = sb + TBYTES, sBhi = sb + 2 * TBYTES, sBlo = sb + 3 * TBYTES;

    const int tid = threadIdx.x;
    const int rowBase = blockIdx.y * 128, colBase = blockIdx.x * 128;

    // ---- stage all four tiles (2048 x 16B chunks each; 8 iters per tile) ----
    #pragma unroll
    for (int p = 0; p < 8; p++) {
        const int id  = tid + p * 256;        // 0..2047
        const int row = id >> 4;
        const int kc  = id & 15;              // 16B chunk within row
        const uint32_t so = (uint32_t)(row * 272 + kc * 16);
        const size_t ea = (size_t)(rowBase + row) * GK + kc * 8;
        const size_t eb = (size_t)(colBase + row) * GK + kc * 8;
        cp_async16(sAhi + so, Ahi + ea);
        cp_async16(sAlo + so, Alo + ea);
        cp_async16(sBhi + so, Bhi + eb);
        cp_async16(sBlo + so, Blo + eb);
    }
    cp_commit();
    cp_wait<0>();
    __syncthreads();

    const int wid  = tid >> 5, lane = tid & 31;
    const int wm   = wid & 3, wn = wid >> 2;     // 4 x 2 warp grid
    const int g    = lane >> 2, t = lane & 3;

    float acc[2][8][4];
    #pragma unroll
    for (int mi = 0; mi < 2; mi++)
        #pragma unroll
        for (int nj = 0; nj < 8; nj++)
            #pragma unroll
            for (int e = 0; e < 4; e++) acc[mi][nj][e] = 0.f;

    const uint32_t* SA[2] = {(const uint32_t*)(dsm), (const uint32_t*)(dsm + TBYTES)};
    const uint32_t* SB[2] = {(const uint32_t*)(dsm + 2 * TBYTES), (const uint32_t*)(dsm + 3 * TBYTES)};
    // passes: (Ahi,Bhi), (Ahi,Blo), (Alo,Bhi)
    const int pa[3] = {0, 0, 1}, pb[3] = {0, 1, 0};

    const int ar0 = wm * 32 + g;          // A row for mi=0 (a0/a2); +8 for a1/a3; +16 for mi=1
    const int bn0 = wn * 64 + g;          // B row (n) for nj=0; +8 per nj

    #pragma unroll
    for (int ps = 0; ps < 3; ps++) {
        const uint32_t* A = SA[pa[ps]];
        const uint32_t* B = SB[pb[ps]];
        #pragma unroll
        for (int s = 0; s < 8; s++) {                 // k-step of 16
            const int kw = s * 8 + t;                 // word offset in row
            uint32_t a[2][4];
            #pragma unroll
            for (int mi = 0; mi < 2; mi++) {
                const int r = ar0 + mi * 16;
                a[mi][0] = A[r * TPITCH_W + kw];
                a[mi][1] = A[(r + 8) * TPITCH_W + kw];
                a[mi][2] = A[r * TPITCH_W + kw + 4];
                a[mi][3] = A[(r + 8) * TPITCH_W + kw + 4];
            }
            #pragma unroll
            for (int nj = 0; nj < 8; nj++) {
                uint32_t b[2];
                const int n = bn0 + nj * 8;
                b[0] = B[n * TPITCH_W + kw];
                b[1] = B[n * TPITCH_W + kw + 4];
                mma_bf16(acc[0][nj], a[0], b);
                mma_bf16(acc[1][nj], a[1], b);
            }
        }
    }

    // ---- epilogue: bias + store fp32 ----
    #pragma unroll
    for (int mi = 0; mi < 2; mi++) {
        const int row = rowBase + wm * 32 + mi * 16 + g;
        #pragma unroll
        for (int nj = 0; nj < 8; nj++) {
            const int col = colBase + wn * 64 + nj * 8 + 2 * t;
            const float bx = bias[col], by = bias[col + 1];
            float2 v0 = {acc[mi][nj][0] + bx, acc[mi][nj][1] + by};
            float2 v1 = {acc[mi][nj][2] + bx, acc[mi][nj][3] + by};
            *(float2*)&C[(size_t)row * Ntot + col] = v0;
            *(float2*)&C[(size_t)(row + 8) * Ntot + col] = v1;
        }
    }
}

// ---------------------------------------------------------------------------
// split fp32 -> bf16 hi/lo (elementwise, float4 vectorized)
// ---------------------------------------------------------------------------
__global__ __launch_bounds__(256) void split_kernel(
    const float* __restrict__ src, __nv_bfloat16* __restrict__ hi,
    __nv_bfloat16* __restrict__ lo, int n4)
{
    int i = blockIdx.x * 256 + threadIdx.x;
    if (i >= n4) return;
    float4 v = ((const float4*)src)[i];
    float vv[4] = {v.x, v.y, v.z, v.w};
    __nv_bfloat162 h2[2], l2[2];
    #pragma unroll
    for (int p = 0; p < 2; p++) {
        __nv_bfloat16 h0 = __float2bfloat16(vv[2 * p + 0]);
        __nv_bfloat16 h1 = __float2bfloat16(vv[2 * p + 1]);
        h2[p] = __nv_bfloat162(h0, h1);
        l2[p] = __nv_bfloat162(__float2bfloat16(vv[2 * p + 0] - __bfloat162float(h0)),
                               __float2bfloat16(vv[2 * p + 1] - __bfloat162float(h1)));
    }
    ((__nv_bfloat162*)hi)[2 * i + 0] = h2[0];
    ((__nv_bfloat162*)hi)[2 * i + 1] = h2[1];
    ((__nv_bfloat162*)lo)[2 * i + 0] = l2[0];
    ((__nv_bfloat162*)lo)[2 * i + 1] = l2[1];
}

// transpose + split: w [K=128][N] -> wt_hi/lo [N][128]
__global__ __launch_bounds__(256) void transpose_split_kernel(
    const float* __restrict__ w, __nv_bfloat16* __restrict__ hi,
    __nv_bfloat16* __restrict__ lo, int N)
{
    int idx = blockIdx.x * 256 + threadIdx.x;   // n*128 + k
    if (idx >= N * GK) return;
    int n = idx >> 7, k = idx & 127;
    float v = w[k * N + n];
    __nv_bfloat16 h = __float2bfloat16(v);
    hi[idx] = h;
    lo[idx] = __float2bfloat16(v - __bfloat162float(h));
}

// ---------------------------------------------------------------------------
// Neighborhood attention (compute identical to R5/R6 passing kernel).
// Output written as bf16 hi/lo split for the mma proj GEMM.
// ---------------------------------------------------------------------------
#define TQ   7
#define WIN  13
#define WPOS 169

__global__ __launch_bounds__(64) void natten_kernel(
    const float* __restrict__ qkv, const float* __restrict__ rpb,
    __nv_bfloat16* __restrict__ ohi, __nv_bfloat16* __restrict__ olo)
{
    __shared__ float Ks[HD * WPOS];
    __shared__ float Vs[HD * WPOS];
    __shared__ float Bsm[WPOS];

    const int tid = threadIdx.x;
    const int bn  = blockIdx.y;
    const int n   = bn & 3;
    const int b   = bn >> 2;
    const int ty  = blockIdx.x >> 3;
    const int tx  = blockIdx.x & 7;
    const int ti0 = ty * TQ;
    const int tj0 = tx * TQ;

    const int wi0 = max(ti0 - NB, 0);
    const int wi1 = min(ti0 + NB, HH - KS) + (KS - 1);
    const int wj0 = max(tj0 - NB, 0);
    const int wj1 = min(tj0 + NB, WW - KS) + (KS - 1);
    const int nr = wi1 - wi0 + 1;
    const int nc = wj1 - wj0 + 1;

    for (int i = tid; i < WPOS; i += 64) Bsm[i] = rpb[n * WPOS + i];

    const int npos = nr * nc;
    for (int idx = tid; idx < npos * 8; idx += 64) {
        int pos = idx >> 3, f = idx & 7;
        int r = pos / nc, c = pos - r * nc;
        int tok = (b * HH + wi0 + r) * WW + (wj0 + c);
        const float* base = qkv + tok * QKVN + n * HD + f * 4;
        float4 kv = *(const float4*)(base + CC);
        float4 vv = *(const float4*)(base + 2 * CC);
        int spos = r * WIN + c;
        Ks[(f * 4 + 0) * WPOS + spos] = kv.x;
        Ks[(f * 4 + 1) * WPOS + spos] = kv.y;
        Ks[(f * 4 + 2) * WPOS + spos] = kv.z;
        Ks[(f * 4 + 3) * WPOS + spos] = kv.w;
        Vs[(f * 4 + 0) * WPOS + spos] = vv.x;
        Vs[(f * 4 + 1) * WPOS + spos] = vv.y;
        Vs[(f * 4 + 2) * WPOS + spos] = vv.z;
        Vs[(f * 4 + 3) * WPOS + spos] = vv.w;
    }
    __syncthreads();

    if (tid >= TQ * TQ) return;

    const int qi = tid / TQ, qj = tid - (tid / TQ) * TQ;
    const int i = ti0 + qi, j = tj0 + qj;
    const int si = min(max(i - NB, 0), HH - KS);
    const int sj = min(max(j - NB, 0), WW - KS);
    const int pbase = (si - wi0) * WIN + (sj - wj0);
    const int bbase = (si - i + 2 * NB) * WIN + (sj - j + 2 * NB);
    const int tok = (b * HH + i) * WW + j;

    float q[HD];
    {
        const float4* qp = (const float4*)(qkv + tok * QKVN + n * HD);
        #pragma unroll
        for (int f = 0; f < 8; f++) {
            float4 t = qp[f];
            q[4 * f + 0] = t.x * SCALE;
            q[4 * f + 1] = t.y * SCALE;
            q[4 * f + 2] = t.z * SCALE;
            q[4 * f + 3] = t.w * SCALE;
        }
    }

    float sc[KS * KS];
    float mx = -1e30f;
    #pragma unroll
    for (int p = 0; p < KS; p++) {
        #pragma unroll
        for (int r = 0; r < KS; r++) {
            const int pos = pbase + p * WIN + r;
            float s = 0.f;
            #pragma unroll
            for (int d = 0; d < HD; d++) s += q[d] * Ks[d * WPOS + pos];
            s += Bsm[bbase + p * WIN + r];
            sc[p * KS + r] = s;
            mx = fmaxf(mx, s);
        }
    }

    float sum = 0.f;
    #pragma unroll
    for (int t = 0; t < KS * KS; t++) {
        sc[t] = __expf(sc[t] - mx);
        sum += sc[t];
    }
    float acc[HD];
    #pragma unroll
    for (int d = 0; d < HD; d++) acc[d] = 0.f;
    #pragma unroll
    for (int p = 0; p < KS; p++) {
        #pragma unroll
        for (int r = 0; r < KS; r++) {
            const float w = sc[p * KS + r];
            const int pos = pbase + p * WIN + r;
            #pragma unroll
            for (int d = 0; d < HD; d++) acc[d] += w * Vs[d * WPOS + pos];
        }
    }
    const float inv = 1.f / sum;
    __nv_bfloat162* hp = (__nv_bfloat162*)(ohi + (size_t)tok * CC + n * HD);
    __nv_bfloat162* lp = (__nv_bfloat162*)(olo + (size_t)tok * CC + n * HD);
    #pragma unroll
    for (int d2 = 0; d2 < HD / 2; d2++) {
        float v0 = acc[2 * d2 + 0] * inv;
        float v1 = acc[2 * d2 + 1] * inv;
        __nv_bfloat16 h0 = __float2bfloat16(v0);
        __nv_bfloat16 h1 = __float2bfloat16(v1);
        hp[d2] = __nv_bfloat162(h0, h1);
        lp[d2] = __nv_bfloat162(__float2bfloat16(v0 - __bfloat162float(h0)),
                                __float2bfloat16(v1 - __bfloat162float(h1)));
    }
}

// ---------------------------------------------------------------------------
extern "C" void kernel_launch(void* const* d_in, const int* in_sizes, int n_in,
                              void* d_out, int out_size)
{
    const float* x      = (const float*)d_in[0];
    const float* w_qkv  = (const float*)d_in[1];
    const float* b_qkv  = (const float*)d_in[2];
    const float* rpb    = (const float*)d_in[3];
    const float* w_proj = (const float*)d_in[4];
    const float* b_proj = (const float*)d_in[5];
    float* out = (float*)d_out;

    __nv_bfloat16 *xhi, *xlo, *wqh, *wql, *wph, *wpl, *ahi, *alo;
    float* qkv;
    cudaGetSymbolAddress((void**)&xhi, g_xhi_);
    cudaGetSymbolAddress((void**)&xlo, g_xlo_);
    cudaGetSymbolAddress((void**)&wqh, g_wqh_);
    cudaGetSymbolAddress((void**)&wql, g_wql_);
    cudaGetSymbolAddress((void**)&wph, g_wph_);
    cudaGetSymbolAddress((void**)&wpl, g_wpl_);
    cudaGetSymbolAddress((void**)&ahi, g_ahi_);
    cudaGetSymbolAddress((void**)&alo, g_alo_);
    cudaGetSymbolAddress((void**)&qkv, g_qkv);

    cudaFuncSetAttribute(gemm_mma_kernel, cudaFuncAttributeMaxDynamicSharedMemorySize, SM_TOTAL);

    // prep: split x, transpose+split weights
    split_kernel<<<(MTOK * CC / 4 + 255) / 256, 256>>>(x, xhi, xlo, MTOK * CC / 4);
    transpose_split_kernel<<<(QKVN * GK + 255) / 256, 256>>>(w_qkv, wqh, wql, QKVN);
    transpose_split_kernel<<<(CC * GK + 255) / 256, 256>>>(w_proj, wph, wpl, CC);

    // 1) qkv = x @ w_qkv + b_qkv  (tensor cores, split bf16)
    dim3 g1(QKVN / 128, MTOK / 128);
    gemm_mma_kernel<<<g1, 256, SM_TOTAL>>>(xhi, xlo, wqh, wql, b_qkv, qkv, QKVN);

    // 2) neighborhood attention -> att hi/lo (bf16 split)
    dim3 g2(64, BB * NHD);
    natten_kernel<<<g2, 64>>>(qkv, rpb, ahi, alo);

    // 3) out = att @ w_proj + b_proj (tensor cores, split bf16)
    dim3 g3(CC / 128, MTOK / 128);
    gemm_mma_kernel<<<g3, 256, SM_TOTAL>>>(ahi, alo, wph, wpl, b_proj, out, CC);
}

// round 13
// speedup vs baseline: 1.2077x; 1.0359x over previous
#include <cuda_runtime.h>
#include <cuda_bf16.h>
#include <cstdint>

// Problem constants
#define BB   4
#define HH   56
#define WW   56
#define CC   128
#define NHD  4
#define HD   32
#define KS   7
#define NB   3
#define MTOK (BB*HH*WW)     // 12544
#define QKVN (3*CC)         // 384
#define GK   128
#define SCALE 0.17677669529663687f

// ---------------- scratch ---------------------------------------------------
__device__ uint4 g_xhi_[MTOK*CC*2/16];
__device__ uint4 g_xlo_[MTOK*CC*2/16];
__device__ uint4 g_wqh_[QKVN*GK*2/16];
__device__ uint4 g_wql_[QKVN*GK*2/16];
__device__ uint4 g_wph_[CC*GK*2/16];
__device__ uint4 g_wpl_[CC*GK*2/16];
__device__ uint4 g_ahi_[MTOK*CC*2/16];
__device__ uint4 g_alo_[MTOK*CC*2/16];
__device__ float g_qkv[MTOK * QKVN];

// ---------------- helpers ---------------------------------------------------
__device__ __forceinline__ void cp_async16(uint32_t smem_dst, const void* gmem_src) {
    asm volatile("cp.async.cg.shared.global [%0], [%1], 16;\n" :: "r"(smem_dst), "l"(gmem_src));
}
__device__ __forceinline__ void cp_commit() { asm volatile("cp.async.commit_group;\n"); }
template<int N> __device__ __forceinline__ void cp_wait() {
    asm volatile("cp.async.wait_group %0;\n" :: "n"(N));
}
__device__ __forceinline__ void mma_bf16(float* c, const uint32_t* a, const uint32_t* b) {
    asm volatile(
        "mma.sync.aligned.m16n8k16.row.col.f32.bf16.bf16.f32 "
        "{%0,%1,%2,%3}, {%4,%5,%6,%7}, {%8,%9}, {%0,%1,%2,%3};\n"
        : "+f"(c[0]), "+f"(c[1]), "+f"(c[2]), "+f"(c[3])
        : "r"(a[0]), "r"(a[1]), "r"(a[2]), "r"(a[3]), "r"(b[0]), "r"(b[1]));
}

// Smem tile geometry: 64 rows x 128 bf16, row padded to 136 bf16 (272 B, 68 words).
#define TPITCH_W 68
#define TBYTES   17408              // 64 * 272
#define SM_TOTAL (4 * TBYTES)       // Ahi, Alo, Bhi, Blo = 69632

// ---------------------------------------------------------------------------
// Split-bf16 mma GEMM, 64x64 CTA tile, 128 threads (4 warps of 32x32).
// C[M, Ntot](fp32) = A[M,128] x B[Ntot,128]^T + bias
// D = Ahi*Bhi + Ahi*Blo + Alo*Bhi.
// ---------------------------------------------------------------------------
__global__ __launch_bounds__(128) void gemm_mma_kernel(
    const __nv_bfloat16* __restrict__ Ahi, const __nv_bfloat16* __restrict__ Alo,
    const __nv_bfloat16* __restrict__ Bhi, const __nv_bfloat16* __restrict__ Blo,
    const float* __restrict__ bias, float* __restrict__ C, int Ntot)
{
    extern __shared__ char dsm[];
    const uint32_t sb = (uint32_t)__cvta_generic_to_shared(dsm);
    const uint32_t sAhi = sb, sAlo = sb + TBYTES, sBhi = sb + 2 * TBYTES, sBlo = sb + 3 * TBYTES;

    const int tid = threadIdx.x;
    const int rowBase = blockIdx.y * 64, colBase = blockIdx.x * 64;

    // ---- stage four 64x128 bf16 tiles (1024 x 16B chunks each) ----
    #pragma unroll
    for (int p = 0; p < 8; p++) {
        const int id  = tid + p * 128;        // 0..1023
        const int row = id >> 4;
        const int kc  = id & 15;
        const uint32_t so = (uint32_t)(row * 272 + kc * 16);
        const size_t ea = (size_t)(rowBase + row) * GK + kc * 8;
        const size_t eb = (size_t)(colBase + row) * GK + kc * 8;
        cp_async16(sAhi + so, Ahi + ea);
        cp_async16(sAlo + so, Alo + ea);
        cp_async16(sBhi + so, Bhi + eb);
        cp_async16(sBlo + so, Blo + eb);
    }
    cp_commit();
    cp_wait<0>();
    __syncthreads();

    const int wid = tid >> 5, lane = tid & 31;
    const int wm = wid & 1, wn = wid >> 1;        // 2 x 2 warp grid, 32x32 tiles
    const int g = lane >> 2, t = lane & 3;

    float acc[2][4][4];
    #pragma unroll
    for (int mi = 0; mi < 2; mi++)
        #pragma unroll
        for (int nj = 0; nj < 4; nj++)
            #pragma unroll
            for (int e = 0; e < 4; e++) acc[mi][nj][e] = 0.f;

    const uint32_t* SA[2] = {(const uint32_t*)(dsm), (const uint32_t*)(dsm + TBYTES)};
    const uint32_t* SB[2] = {(const uint32_t*)(dsm + 2 * TBYTES), (const uint32_t*)(dsm + 3 * TBYTES)};
    const int pa[3] = {0, 0, 1}, pb[3] = {0, 1, 0};

    const int ar0 = wm * 32 + g;
    const int bn0 = wn * 32 + g;

    #pragma unroll
    for (int ps = 0; ps < 3; ps++) {
        const uint32_t* A = SA[pa[ps]];
        const uint32_t* B = SB[pb[ps]];
        #pragma unroll
        for (int s = 0; s < 8; s++) {
            const int kw = s * 8 + t;
            uint32_t a[2][4];
            #pragma unroll
            for (int mi = 0; mi < 2; mi++) {
                const int r = ar0 + mi * 16;
                a[mi][0] = A[r * TPITCH_W + kw];
                a[mi][1] = A[(r + 8) * TPITCH_W + kw];
                a[mi][2] = A[r * TPITCH_W + kw + 4];
                a[mi][3] = A[(r + 8) * TPITCH_W + kw + 4];
            }
            #pragma unroll
            for (int nj = 0; nj < 4; nj++) {
                uint32_t b[2];
                const int n = bn0 + nj * 8;
                b[0] = B[n * TPITCH_W + kw];
                b[1] = B[n * TPITCH_W + kw + 4];
                mma_bf16(acc[0][nj], a[0], b);
                mma_bf16(acc[1][nj], a[1], b);
            }
        }
    }

    #pragma unroll
    for (int mi = 0; mi < 2; mi++) {
        const int row = rowBase + wm * 32 + mi * 16 + g;
        #pragma unroll
        for (int nj = 0; nj < 4; nj++) {
            const int col = colBase + wn * 32 + nj * 8 + 2 * t;
            const float bx = bias[col], by = bias[col + 1];
            float2 v0 = {acc[mi][nj][0] + bx, acc[mi][nj][1] + by};
            float2 v1 = {acc[mi][nj][2] + bx, acc[mi][nj][3] + by};
            *(float2*)&C[(size_t)row * Ntot + col] = v0;
            *(float2*)&C[(size_t)(row + 8) * Ntot + col] = v1;
        }
    }
}

// ---------------------------------------------------------------------------
// prep kernels (unchanged)
// ---------------------------------------------------------------------------
__global__ __launch_bounds__(256) void split_kernel(
    const float* __restrict__ src, __nv_bfloat16* __restrict__ hi,
    __nv_bfloat16* __restrict__ lo, int n4)
{
    int i = blockIdx.x * 256 + threadIdx.x;
    if (i >= n4) return;
    float4 v = ((const float4*)src)[i];
    float vv[4] = {v.x, v.y, v.z, v.w};
    __nv_bfloat162 h2[2], l2[2];
    #pragma unroll
    for (int p = 0; p < 2; p++) {
        __nv_bfloat16 h0 = __float2bfloat16(vv[2 * p + 0]);
        __nv_bfloat16 h1 = __float2bfloat16(vv[2 * p + 1]);
        h2[p] = __nv_bfloat162(h0, h1);
        l2[p] = __nv_bfloat162(__float2bfloat16(vv[2 * p + 0] - __bfloat162float(h0)),
                               __float2bfloat16(vv[2 * p + 1] - __bfloat162float(h1)));
    }
    ((__nv_bfloat162*)hi)[2 * i + 0] = h2[0];
    ((__nv_bfloat162*)hi)[2 * i + 1] = h2[1];
    ((__nv_bfloat162*)lo)[2 * i + 0] = l2[0];
    ((__nv_bfloat162*)lo)[2 * i + 1] = l2[1];
}

__global__ __launch_bounds__(256) void transpose_split_kernel(
    const float* __restrict__ w, __nv_bfloat16* __restrict__ hi,
    __nv_bfloat16* __restrict__ lo, int N)
{
    int idx = blockIdx.x * 256 + threadIdx.x;
    if (idx >= N * GK) return;
    int n = idx >> 7, k = idx & 127;
    float v = w[k * N + n];
    __nv_bfloat16 h = __float2bfloat16(v);
    hi[idx] = h;
    lo[idx] = __float2bfloat16(v - __bfloat162float(h));
}

// ---------------------------------------------------------------------------
// Neighborhood attention v2: warp-per-query.
// Block = 256 threads (8 warps) per (b, head, 7x7 query tile).
// K/V staged [pos][d] with pitch 33 (QK: <=2-way conflicts; AV: conflict-free).
// QK: lane owns 1-2 key positions; softmax via warp shuffles.
// AV: lane owns output dim d; weights broadcast from smem.
// ---------------------------------------------------------------------------
#define TQ    7
#define WIN   13
#define WPOS  169
#define PITCH 33

__global__ __launch_bounds__(256) void natten_kernel(
    const float* __restrict__ qkv, const float* __restrict__ rpb,
    __nv_bfloat16* __restrict__ ohi, __nv_bfloat16* __restrict__ olo)
{
    __shared__ float Ksm[WPOS * PITCH];   // 22.3 KB
    __shared__ float Vsm[WPOS * PITCH];   // 22.3 KB
    __shared__ float Bsm[WPOS];
    __shared__ float Wbuf[8][52];

    const int tid  = threadIdx.x;
    const int wid  = tid >> 5;
    const int lane = tid & 31;
    const int bn   = blockIdx.y;
    const int n    = bn & 3;
    const int b    = bn >> 2;
    const int ty   = blockIdx.x >> 3;
    const int tx   = blockIdx.x & 7;
    const int ti0  = ty * TQ;
    const int tj0  = tx * TQ;

    const int wi0 = max(ti0 - NB, 0);
    const int wi1 = min(ti0 + NB, HH - KS) + (KS - 1);
    const int wj0 = max(tj0 - NB, 0);
    const int wj1 = min(tj0 + NB, WW - KS) + (KS - 1);
    const int nr = wi1 - wi0 + 1;   // <= 13
    const int nc = wj1 - wj0 + 1;   // <= 13

    for (int i = tid; i < WPOS; i += 256) Bsm[i] = rpb[n * WPOS + i];

    // stage K,V as [pos][d], pos = r*WIN + c; coalesced 128B rows from gmem
    const int npos = nr * nc;
    for (int idx = tid; idx < npos * HD; idx += 256) {
        const int pos = idx >> 5, d = idx & 31;
        const int r = pos / nc, c = pos - r * nc;
        const int tok = (b * HH + wi0 + r) * WW + (wj0 + c);
        const float* base = qkv + (size_t)tok * QKVN + n * HD + d;
        const int sp = (r * WIN + c) * PITCH + d;
        Ksm[sp] = base[CC];
        Vsm[sp] = base[2 * CC];
    }
    __syncthreads();

    // warp-per-query: warp handles queries wid, wid+8, ...
    for (int q0 = wid; q0 < TQ * TQ; q0 += 8) {
        const int qi = q0 / TQ, qj = q0 - qi * TQ;
        const int i = ti0 + qi, j = tj0 + qj;
        const int si = min(max(i - NB, 0), HH - KS);
        const int sj = min(max(j - NB, 0), WW - KS);
        const int pbase = (si - wi0) * WIN + (sj - wj0);
        const int bbase = (si - i + 2 * NB) * WIN + (sj - j + 2 * NB);
        const int tok = (b * HH + i) * WW + j;

        // q (broadcast loads, all lanes same addresses)
        const float* qp = qkv + (size_t)tok * QKVN + n * HD;
        float qv[HD];
        #pragma unroll
        for (int d = 0; d < HD; d++) qv[d] = qp[d] * SCALE;

        // scores: lane owns positions lane and lane+32
        const int pa = lane / 7, ra = lane - pa * 7;
        float sa;
        {
            const int wpos = pbase + pa * WIN + ra;
            float s = 0.f;
            #pragma unroll
            for (int d = 0; d < HD; d++) s += qv[d] * Ksm[wpos * PITCH + d];
            sa = s + Bsm[bbase + pa * WIN + ra];
        }
        float sb = -1e30f;
        if (lane < 17) {
            const int p49 = lane + 32;
            const int pb = p49 / 7, rb = p49 - pb * 7;
            const int wpos = pbase + pb * WIN + rb;
            float s = 0.f;
            #pragma unroll
            for (int d = 0; d < HD; d++) s += qv[d] * Ksm[wpos * PITCH + d];
            sb = s + Bsm[bbase + pb * WIN + rb];
        }

        // warp max
        float m = fmaxf(sa, sb);
        #pragma unroll
        for (int o = 16; o > 0; o >>= 1) m = fmaxf(m, __shfl_xor_sync(0xFFFFFFFFu, m, o));

        const float ea = __expf(sa - m);
        const float eb = (lane < 17) ? __expf(sb - m) : 0.f;

        float sum = ea + eb;
        #pragma unroll
        for (int o = 16; o > 0; o >>= 1) sum += __shfl_xor_sync(0xFFFFFFFFu, sum, o);

        Wbuf[wid][lane] = ea;
        if (lane < 17) Wbuf[wid][32 + lane] = eb;
        __syncwarp();

        // AV: lane owns output dim d = lane
        float o = 0.f;
        #pragma unroll
        for (int p49 = 0; p49 < KS * KS; p49++) {
            const int p = p49 / KS, r = p49 - p * KS;   // compile-time
            const int wpos = pbase + p * WIN + r;
            o += Wbuf[wid][p49] * Vsm[wpos * PITCH + lane];
        }
        o *= __frcp_rn(sum);

        const __nv_bfloat16 h = __float2bfloat16(o);
        ohi[(size_t)tok * CC + n * HD + lane] = h;
        olo[(size_t)tok * CC + n * HD + lane] = __float2bfloat16(o - __bfloat162float(h));
        __syncwarp();
    }
}

// ---------------------------------------------------------------------------
extern "C" void kernel_launch(void* const* d_in, const int* in_sizes, int n_in,
                              void* d_out, int out_size)
{
    const float* x      = (const float*)d_in[0];
    const float* w_qkv  = (const float*)d_in[1];
    const float* b_qkv  = (const float*)d_in[2];
    const float* rpb    = (const float*)d_in[3];
    const float* w_proj = (const float*)d_in[4];
    const float* b_proj = (const float*)d_in[5];
    float* out = (float*)d_out;

    __nv_bfloat16 *xhi, *xlo, *wqh, *wql, *wph, *wpl, *ahi, *alo;
    float* qkv;
    cudaGetSymbolAddress((void**)&xhi, g_xhi_);
    cudaGetSymbolAddress((void**)&xlo, g_xlo_);
    cudaGetSymbolAddress((void**)&wqh, g_wqh_);
    cudaGetSymbolAddress((void**)&wql, g_wql_);
    cudaGetSymbolAddress((void**)&wph, g_wph_);
    cudaGetSymbolAddress((void**)&wpl, g_wpl_);
    cudaGetSymbolAddress((void**)&ahi, g_ahi_);
    cudaGetSymbolAddress((void**)&alo, g_alo_);
    cudaGetSymbolAddress((void**)&qkv, g_qkv);

    cudaFuncSetAttribute(gemm_mma_kernel, cudaFuncAttributeMaxDynamicSharedMemorySize, SM_TOTAL);

    split_kernel<<<(MTOK * CC / 4 + 255) / 256, 256>>>(x, xhi, xlo, MTOK * CC / 4);
    transpose_split_kernel<<<(QKVN * GK + 255) / 256, 256>>>(w_qkv, wqh, wql, QKVN);
    transpose_split_kernel<<<(CC * GK + 255) / 256, 256>>>(w_proj, wph, wpl, CC);

    // 1) qkv = x @ w_qkv + b_qkv   (grid 6 x 196)
    dim3 g1(QKVN / 64, MTOK / 64);
    gemm_mma_kernel<<<g1, 128, SM_TOTAL>>>(xhi, xlo, wqh, wql, b_qkv, qkv, QKVN);

    // 2) neighborhood attention -> att hi/lo
    dim3 g2(64, BB * NHD);
    natten_kernel<<<g2, 256>>>(qkv, rpb, ahi, alo);

    // 3) out = att @ w_proj + b_proj  (grid 2 x 196)
    dim3 g3(CC / 64, MTOK / 64);
    gemm_mma_kernel<<<g3, 128, SM_TOTAL>>>(ahi, alo, wph, wpl, b_proj, out, CC);
}